// round 9
// baseline (speedup 1.0000x reference)
#include <cuda_runtime.h>
#include <cuda_bf16.h>

#define N_NODES 100000
#define N_EDGES 1600000
#define IN_DIM  256
#define HIDDEN  64

#define FUSED_BLOCKS 12500   // 8 warps/block * 12500 = 100000 warps = 1 per node
#define EDGE_PAIRS   (N_EDGES / 2)   // 800000 int2 loads

// Scratch (__device__ globals; zero at module load; k_out re-zeros for replay)
__device__ float g_c;                          // b.w2 + b2
__device__ float g_deg[N_NODES];               // edge count (self loop = +1 in dinv)
__device__ float g_ss[N_NODES];                // raw s[v]; k_norm multiplies dinv in
__device__ float g_dinv[N_NODES];
__device__ float g_t[N_NODES];                 // edge-aggregated ss[src]

// K1: fused. Every block: (a) compute u = W@w2 into smem (redundant, L2-cached),
//     (b) first 800K threads chip in one int2 of degree atomics (independent of u),
//     (c) warp-per-node dot s[v] = x[v].u  (raw; dinv applied later).
__global__ void __launch_bounds__(256) k_fused(
        const float* __restrict__ x, const int* __restrict__ dst,
        const float* __restrict__ W, const float* __restrict__ w2) {
    __shared__ __align__(16) float s_u[IN_DIM];
    __shared__ __align__(16) float s_w2[HIDDEN];

    const int tid  = threadIdx.x;
    const int gtid = blockIdx.x * 256 + tid;

    // (b) degree slice — fully independent, issued first so it overlaps everything
    if (gtid < EDGE_PAIRS) {
        int2 p = ((const int2*)dst)[gtid];
        if ((unsigned)p.x < (unsigned)N_NODES) atomicAdd(&g_deg[p.x], 1.0f);
        if ((unsigned)p.y < (unsigned)N_NODES) atomicAdd(&g_deg[p.y], 1.0f);
    }

    // (a) u into shared
    if (tid < HIDDEN) s_w2[tid] = w2[tid];
    __syncthreads();
    {
        const float4* wr = (const float4*)(W + (size_t)tid * HIDDEN);
        float acc = 0.f;
#pragma unroll
        for (int q = 0; q < HIDDEN / 4; q++) {
            float4 wv = wr[q];
            acc += wv.x * s_w2[q * 4 + 0] + wv.y * s_w2[q * 4 + 1]
                 + wv.z * s_w2[q * 4 + 2] + wv.w * s_w2[q * 4 + 3];
        }
        s_u[tid] = acc;
    }
    __syncthreads();

    // (c) dot: warp per node, 64B per lane (2 independent float4 loads)
    const int node = gtid >> 5;          // 0..99999 exactly
    const int lane = tid & 31;
    const float4* xp = (const float4*)(x + (size_t)node * IN_DIM);
    const float4* up = (const float4*)s_u;
    float4 a0 = xp[lane];
    float4 a1 = xp[lane + 32];
    float4 u0 = up[lane];
    float4 u1 = up[lane + 32];
    float acc = a0.x*u0.x + a0.y*u0.y + a0.z*u0.z + a0.w*u0.w
              + a1.x*u1.x + a1.y*u1.y + a1.z*u1.z + a1.w*u1.w;
#pragma unroll
    for (int o = 16; o; o >>= 1) acc += __shfl_xor_sync(0xffffffffu, acc, o);
    if (lane == 0) g_ss[node] = acc;
}

// K2: dinv = rsqrt(1+deg); ss *= dinv. Block 0 thread 0 computes c.
__global__ void __launch_bounds__(256) k_norm(const float* __restrict__ b,
                                              const float* __restrict__ w2,
                                              const float* __restrict__ b2) {
    int v = blockIdx.x * 256 + threadIdx.x;
    if (v < N_NODES) {
        float di = rsqrtf(1.0f + g_deg[v]);
        g_dinv[v] = di;
        g_ss[v] *= di;
    }
    if (blockIdx.x == 0 && threadIdx.x == 0) {
        float cc = b2[0];
#pragma unroll
        for (int h = 0; h < HIDDEN; h++) cc += b[h] * w2[h];
        g_c = cc;
    }
}

// K3: scatter ss[src] into t[dst]; 2 edges/thread via int2
__global__ void __launch_bounds__(256) k_scatter(const int* __restrict__ src,
                                                 const int* __restrict__ dst) {
    int i = blockIdx.x * 256 + threadIdx.x;
    if (i < EDGE_PAIRS) {
        int2 s = ((const int2*)src)[i];
        int2 d = ((const int2*)dst)[i];
        float v0 = ((unsigned)s.x < (unsigned)N_NODES) ? g_ss[s.x] : 0.f;
        float v1 = ((unsigned)s.y < (unsigned)N_NODES) ? g_ss[s.y] : 0.f;
        if ((unsigned)d.x < (unsigned)N_NODES) atomicAdd(&g_t[d.x], v0);
        if ((unsigned)d.y < (unsigned)N_NODES) atomicAdd(&g_t[d.y], v1);
    }
}

// K4: out = sigmoid(dinv*(t+ss)+c); reset g_deg/g_t for next replay
__global__ void __launch_bounds__(256) k_out(float* __restrict__ out) {
    int v = blockIdx.x * 256 + threadIdx.x;
    if (v < N_NODES) {
        float z = g_dinv[v] * (g_t[v] + g_ss[v]) + g_c;
        out[v] = 1.0f / (1.0f + expf(-z));
        g_deg[v] = 0.0f;
        g_t[v] = 0.0f;
    }
}

extern "C" void kernel_launch(void* const* d_in, const int* in_sizes, int n_in,
                              void* d_out, int out_size) {
    const float* x   = (const float*)d_in[0];
    const int*   ei  = (const int*)d_in[1];   // [2, N_EDGES], materialized as int32
    const float* W   = (const float*)d_in[2];
    const float* b   = (const float*)d_in[3];
    const float* w2  = (const float*)d_in[4];
    const float* b2  = (const float*)d_in[5];
    float*       out = (float*)d_out;

    const int* src = ei;
    const int* dst = ei + N_EDGES;

    k_fused<<<FUSED_BLOCKS, 256>>>(x, dst, W, w2);
    k_norm<<<(N_NODES + 255) / 256, 256>>>(b, w2, b2);
    k_scatter<<<(EDGE_PAIRS + 255) / 256, 256>>>(src, dst);
    k_out<<<(N_NODES + 255) / 256, 256>>>(out);
}

// round 10
// speedup vs baseline: 4.1726x; 4.1726x over previous
#include <cuda_runtime.h>
#include <cuda_bf16.h>

#define N_NODES 100000
#define N_EDGES 1600000
#define IN_DIM  256
#define HIDDEN  64

#define DOT_BLOCKS 12500          // 8 warps/block -> warp per node
#define EDGE_PAIRS (N_EDGES / 2)  // 800000 int2 loads

// Scratch (__device__ globals; zero at module load; k_out re-zeros for replay)
__device__ __align__(16) float g_u[IN_DIM];   // W @ w2
__device__ float g_c;                          // b.w2 + b2
__device__ float g_deg[N_NODES];               // edge count (self loop = +1 in dinv)
__device__ float g_ss[N_NODES];                // RAW s[v] (dinv applied by consumers)
__device__ float g_t[N_NODES];                 // edge-aggregated normalized ss[src]

// K1: single block computes u = W@w2 (256 threads) and c = b.w2 + b2
__global__ void __launch_bounds__(256) k_prep(
        const float* __restrict__ W, const float* __restrict__ b,
        const float* __restrict__ w2, const float* __restrict__ b2) {
    __shared__ __align__(16) float s_w2[HIDDEN];
    int i = threadIdx.x;               // 256 == IN_DIM
    if (i < HIDDEN) s_w2[i] = w2[i];
    __syncthreads();
    const float4* wr = (const float4*)(W + (size_t)i * HIDDEN);
    float acc = 0.f;
#pragma unroll
    for (int q = 0; q < HIDDEN / 4; q++) {
        float4 wv = wr[q];
        acc += wv.x * s_w2[q*4+0] + wv.y * s_w2[q*4+1]
             + wv.z * s_w2[q*4+2] + wv.w * s_w2[q*4+3];
    }
    g_u[i] = acc;
    if (i == 0) {
        float cc = b2[0];
        for (int h = 0; h < HIDDEN; h++) cc += b[h] * s_w2[h];
        g_c = cc;
    }
}

// K2: fused dot + degree. First 800K threads each issue one int2 of degree
//     atomics (independent of u, hides under the x stream). Every warp does
//     the raw dot s[v] = x[v].u with u read via __ldg from g_u (tiny, L2/L1).
__global__ void __launch_bounds__(256) k_dotdeg(
        const float* __restrict__ x, const int* __restrict__ dst) {
    const int tid  = threadIdx.x;
    const int gtid = blockIdx.x * 256 + tid;

    // stowaway degree work
    if (gtid < EDGE_PAIRS) {
        int2 p = ((const int2*)dst)[gtid];
        if ((unsigned)p.x < (unsigned)N_NODES) atomicAdd(&g_deg[p.x], 1.0f);
        if ((unsigned)p.y < (unsigned)N_NODES) atomicAdd(&g_deg[p.y], 1.0f);
    }

    // warp-per-node dot
    const int node = gtid >> 5;        // 0..99999 exactly
    const int lane = tid & 31;
    const float4* xp = (const float4*)(x + (size_t)node * IN_DIM);
    const float4* up = (const float4*)g_u;
    float4 a0 = xp[lane];
    float4 a1 = xp[lane + 32];
    float4 u0 = up[lane];
    float4 u1 = up[lane + 32];
    float acc = a0.x*u0.x + a0.y*u0.y + a0.z*u0.z + a0.w*u0.w
              + a1.x*u1.x + a1.y*u1.y + a1.z*u1.z + a1.w*u1.w;
#pragma unroll
    for (int o = 16; o; o >>= 1) acc += __shfl_xor_sync(0xffffffffu, acc, o);
    if (lane == 0) g_ss[node] = acc;   // RAW
}

// K3: t[d] += ss_raw[s] * rsqrt(1 + deg[s]); 2 edges/thread via int2
__global__ void __launch_bounds__(256) k_scatter(const int* __restrict__ src,
                                                 const int* __restrict__ dst) {
    int i = blockIdx.x * 256 + threadIdx.x;
    if (i < EDGE_PAIRS) {
        int2 s = ((const int2*)src)[i];
        int2 d = ((const int2*)dst)[i];
        float v0 = 0.f, v1 = 0.f;
        if ((unsigned)s.x < (unsigned)N_NODES)
            v0 = g_ss[s.x] * rsqrtf(1.0f + g_deg[s.x]);
        if ((unsigned)s.y < (unsigned)N_NODES)
            v1 = g_ss[s.y] * rsqrtf(1.0f + g_deg[s.y]);
        if ((unsigned)d.x < (unsigned)N_NODES) atomicAdd(&g_t[d.x], v0);
        if ((unsigned)d.y < (unsigned)N_NODES) atomicAdd(&g_t[d.y], v1);
    }
}

// K4: out = sigmoid(dinv*(t + ss_raw*dinv) + c); reset g_deg/g_t for replay
__global__ void __launch_bounds__(256) k_out(float* __restrict__ out) {
    int v = blockIdx.x * 256 + threadIdx.x;
    if (v < N_NODES) {
        float deg = g_deg[v];
        float di  = rsqrtf(1.0f + deg);
        float z   = di * (g_t[v] + g_ss[v] * di) + g_c;
        out[v] = 1.0f / (1.0f + expf(-z));
        g_deg[v] = 0.0f;
        g_t[v]   = 0.0f;
    }
}

extern "C" void kernel_launch(void* const* d_in, const int* in_sizes, int n_in,
                              void* d_out, int out_size) {
    const float* x   = (const float*)d_in[0];
    const int*   ei  = (const int*)d_in[1];   // [2, N_EDGES], materialized as int32
    const float* W   = (const float*)d_in[2];
    const float* b   = (const float*)d_in[3];
    const float* w2  = (const float*)d_in[4];
    const float* b2  = (const float*)d_in[5];
    float*       out = (float*)d_out;

    const int* src = ei;
    const int* dst = ei + N_EDGES;

    k_prep<<<1, 256>>>(W, b, w2, b2);
    k_dotdeg<<<DOT_BLOCKS, 256>>>(x, dst);
    k_scatter<<<(EDGE_PAIRS + 255) / 256, 256>>>(src, dst);
    k_out<<<(N_NODES + 255) / 256, 256>>>(out);
}

// round 11
// speedup vs baseline: 4.5746x; 1.0963x over previous
#include <cuda_runtime.h>
#include <cuda_bf16.h>

#define N_NODES 100000
#define N_EDGES 1600000
#define IN_DIM  256
#define HIDDEN  64

#define DOT_BLOCKS 12500          // 8 warps/block -> warp per node
#define EDGE_PAIRS (N_EDGES / 2)  // 800000 int2 loads

// Scratch (__device__ globals; zero at module load; k_out re-zeros for replay)
__device__ __align__(16) float g_u[IN_DIM];    // W @ w2
__device__ float g_c;                           // b.w2 + b2
__device__ __align__(16) float2 g_sd[N_NODES];  // .x = raw s[v], .y = edge count
__device__ __align__(16) float  g_t[N_NODES];   // aggregated normalized ss[src]

// K1: single block computes u = W@w2 (256 threads) and c = b.w2 + b2
__global__ void __launch_bounds__(256) k_prep(
        const float* __restrict__ W, const float* __restrict__ b,
        const float* __restrict__ w2, const float* __restrict__ b2) {
    __shared__ __align__(16) float s_w2[HIDDEN];
    int i = threadIdx.x;               // 256 == IN_DIM
    if (i < HIDDEN) s_w2[i] = w2[i];
    __syncthreads();
    const float4* wr = (const float4*)(W + (size_t)i * HIDDEN);
    float acc = 0.f;
#pragma unroll
    for (int q = 0; q < HIDDEN / 4; q++) {
        float4 wv = wr[q];
        acc += wv.x * s_w2[q*4+0] + wv.y * s_w2[q*4+1]
             + wv.z * s_w2[q*4+2] + wv.w * s_w2[q*4+3];
    }
    g_u[i] = acc;
    if (i == 0) {
        float cc = b2[0];
        for (int h = 0; h < HIDDEN; h++) cc += b[h] * s_w2[h];
        g_c = cc;
    }
}

// K2: fused dot + degree. First 800K threads each issue one int2 of degree
//     atomics into g_sd[..].y (independent of u, hides under the x stream).
//     Every warp computes raw s[v] = x[v].u into g_sd[v].x.
__global__ void __launch_bounds__(256) k_dotdeg(
        const float* __restrict__ x, const int* __restrict__ dst) {
    const int tid  = threadIdx.x;
    const int gtid = blockIdx.x * 256 + tid;

    // stowaway degree work
    if (gtid < EDGE_PAIRS) {
        int2 p = ((const int2*)dst)[gtid];
        if ((unsigned)p.x < (unsigned)N_NODES) atomicAdd(&g_sd[p.x].y, 1.0f);
        if ((unsigned)p.y < (unsigned)N_NODES) atomicAdd(&g_sd[p.y].y, 1.0f);
    }

    // warp-per-node dot
    const int node = gtid >> 5;        // 0..99999 exactly
    const int lane = tid & 31;
    const float4* xp = (const float4*)(x + (size_t)node * IN_DIM);
    const float4* up = (const float4*)g_u;
    float4 a0 = xp[lane];
    float4 a1 = xp[lane + 32];
    float4 u0 = up[lane];
    float4 u1 = up[lane + 32];
    float acc = a0.x*u0.x + a0.y*u0.y + a0.z*u0.z + a0.w*u0.w
              + a1.x*u1.x + a1.y*u1.y + a1.z*u1.z + a1.w*u1.w;
#pragma unroll
    for (int o = 16; o; o >>= 1) acc += __shfl_xor_sync(0xffffffffu, acc, o);
    if (lane == 0) g_sd[node].x = acc;   // RAW (deg may still be updating .y)
}

// K3: t[d] += sd[s].x * rsqrt(1 + sd[s].y); one 8B gather per endpoint
__global__ void __launch_bounds__(256) k_scatter(const int* __restrict__ src,
                                                 const int* __restrict__ dst) {
    int i = blockIdx.x * 256 + threadIdx.x;
    if (i < EDGE_PAIRS) {
        int2 s = ((const int2*)src)[i];
        int2 d = ((const int2*)dst)[i];
        float v0 = 0.f, v1 = 0.f;
        if ((unsigned)s.x < (unsigned)N_NODES) {
            float2 sd = g_sd[s.x];
            v0 = sd.x * rsqrtf(1.0f + sd.y);
        }
        if ((unsigned)s.y < (unsigned)N_NODES) {
            float2 sd = g_sd[s.y];
            v1 = sd.x * rsqrtf(1.0f + sd.y);
        }
        if ((unsigned)d.x < (unsigned)N_NODES) atomicAdd(&g_t[d.x], v0);
        if ((unsigned)d.y < (unsigned)N_NODES) atomicAdd(&g_t[d.y], v1);
    }
}

// K4: 2 nodes/thread. out = sigmoid(dinv*(t + ss*dinv) + c); zero deg + t.
__global__ void __launch_bounds__(256) k_out(float* __restrict__ out) {
    int i = blockIdx.x * 256 + threadIdx.x;   // pair index, 50000 pairs
    if (i < N_NODES / 2) {
        float4 sd2 = ((const float4*)g_sd)[i];      // {ss0,deg0,ss1,deg1}
        float2 t2  = ((const float2*)g_t)[i];
        float di0 = rsqrtf(1.0f + sd2.y);
        float di1 = rsqrtf(1.0f + sd2.w);
        float z0 = di0 * (t2.x + sd2.x * di0) + g_c;
        float z1 = di1 * (t2.y + sd2.z * di1) + g_c;
        float2 o;
        o.x = 1.0f / (1.0f + expf(-z0));
        o.y = 1.0f / (1.0f + expf(-z1));
        ((float2*)out)[i] = o;
        sd2.y = 0.f; sd2.w = 0.f;                   // reset degrees, keep ss
        ((float4*)g_sd)[i] = sd2;
        ((float2*)g_t)[i] = make_float2(0.f, 0.f);
    }
}

extern "C" void kernel_launch(void* const* d_in, const int* in_sizes, int n_in,
                              void* d_out, int out_size) {
    const float* x   = (const float*)d_in[0];
    const int*   ei  = (const int*)d_in[1];   // [2, N_EDGES], materialized as int32
    const float* W   = (const float*)d_in[2];
    const float* b   = (const float*)d_in[3];
    const float* w2  = (const float*)d_in[4];
    const float* b2  = (const float*)d_in[5];
    float*       out = (float*)d_out;

    const int* src = ei;
    const int* dst = ei + N_EDGES;

    k_prep<<<1, 256>>>(W, b, w2, b2);
    k_dotdeg<<<DOT_BLOCKS, 256>>>(x, dst);
    k_scatter<<<(EDGE_PAIRS + 255) / 256, 256>>>(src, dst);
    k_out<<<(N_NODES / 2 + 255) / 256, 256>>>(out);
}

// round 12
// speedup vs baseline: 4.9004x; 1.0712x over previous
#include <cuda_runtime.h>
#include <cuda_bf16.h>

#define N_NODES 100000
#define N_EDGES 1600000
#define IN_DIM  256
#define HIDDEN  64

#define DOT_BLOCKS 12500          // 8 warps/block -> warp per node
#define EDGE_PAIRS (N_EDGES / 2)  // 800000 int2 loads

// Scratch (__device__ globals; zero at module load; k_out re-zeros for replay)
__device__ __align__(16) float g_u[IN_DIM];    // W @ w2
__device__ float g_c;                           // b.w2 + b2
__device__ __align__(16) float2 g_sd[N_NODES];  // .x = raw s[v], .y = edge count
__device__ __align__(16) float  g_t[N_NODES];   // aggregated normalized ss[src]

// K1: single block computes u = W@w2 (256 threads) and c = b.w2 + b2
__global__ void __launch_bounds__(256) k_prep(
        const float* __restrict__ W, const float* __restrict__ b,
        const float* __restrict__ w2, const float* __restrict__ b2) {
    __shared__ __align__(16) float s_w2[HIDDEN];
    int i = threadIdx.x;               // 256 == IN_DIM
    if (i < HIDDEN) s_w2[i] = w2[i];
    __syncthreads();
    const float4* wr = (const float4*)(W + (size_t)i * HIDDEN);
    float acc = 0.f;
#pragma unroll
    for (int q = 0; q < HIDDEN / 4; q++) {
        float4 wv = wr[q];
        acc += wv.x * s_w2[q*4+0] + wv.y * s_w2[q*4+1]
             + wv.z * s_w2[q*4+2] + wv.w * s_w2[q*4+3];
    }
    g_u[i] = acc;
    if (i == 0) {
        float cc = b2[0];
        for (int h = 0; h < HIDDEN; h++) cc += b[h] * s_w2[h];
        g_c = cc;
    }
}

// K2 (PDL secondary of prep): prefetch x + do deg atomics BEFORE the grid
// dependency sync (neither touches g_u); then sync and finish the dot.
__global__ void __launch_bounds__(256) k_dotdeg(
        const float* __restrict__ x, const int* __restrict__ dst) {
    const int tid  = threadIdx.x;
    const int gtid = blockIdx.x * 256 + tid;
    const int node = gtid >> 5;        // 0..99999 exactly
    const int lane = tid & 31;

    // independent prefetch: x rows (streaming hint — keep L2 for the tables)
    const float4* xp = (const float4*)(x + (size_t)node * IN_DIM);
    float4 a0 = __ldcs(&xp[lane]);
    float4 a1 = __ldcs(&xp[lane + 32]);

    // stowaway degree work (writes g_sd[].y only; prep never touches g_sd)
    if (gtid < EDGE_PAIRS) {
        int2 p = ((const int2*)dst)[gtid];
        if ((unsigned)p.x < (unsigned)N_NODES) atomicAdd(&g_sd[p.x].y, 1.0f);
        if ((unsigned)p.y < (unsigned)N_NODES) atomicAdd(&g_sd[p.y].y, 1.0f);
    }

#if __CUDA_ARCH__ >= 900
    cudaGridDependencySynchronize();   // wait for k_prep's g_u
#endif

    const float4* up = (const float4*)g_u;
    float4 u0 = up[lane];
    float4 u1 = up[lane + 32];
    float acc = a0.x*u0.x + a0.y*u0.y + a0.z*u0.z + a0.w*u0.w
              + a1.x*u1.x + a1.y*u1.y + a1.z*u1.z + a1.w*u1.w;
#pragma unroll
    for (int o = 16; o; o >>= 1) acc += __shfl_xor_sync(0xffffffffu, acc, o);
    if (lane == 0) g_sd[node].x = acc;   // RAW
}

// K3 (PDL secondary of dotdeg): prefetch src/dst indices (DRAM, independent),
// then sync, then gather g_sd + atomic into g_t.
__global__ void __launch_bounds__(256) k_scatter(const int* __restrict__ src,
                                                 const int* __restrict__ dst) {
    int i = blockIdx.x * 256 + threadIdx.x;
    int2 s = make_int2(-1, -1), d = make_int2(-1, -1);
    if (i < EDGE_PAIRS) {
        s = ((const int2*)src)[i];
        d = ((const int2*)dst)[i];
    }
#if __CUDA_ARCH__ >= 900
    cudaGridDependencySynchronize();   // wait for k_dotdeg's g_sd
#endif
    if (i < EDGE_PAIRS) {
        float v0 = 0.f, v1 = 0.f;
        if ((unsigned)s.x < (unsigned)N_NODES) {
            float2 sd = g_sd[s.x];
            v0 = sd.x * rsqrtf(1.0f + sd.y);
        }
        if ((unsigned)s.y < (unsigned)N_NODES) {
            float2 sd = g_sd[s.y];
            v1 = sd.x * rsqrtf(1.0f + sd.y);
        }
        if ((unsigned)d.x < (unsigned)N_NODES) atomicAdd(&g_t[d.x], v0);
        if ((unsigned)d.y < (unsigned)N_NODES) atomicAdd(&g_t[d.y], v1);
    }
}

// K4 (PDL secondary of scatter, sync-at-top): 2 nodes/thread.
__global__ void __launch_bounds__(256) k_out(float* __restrict__ out) {
#if __CUDA_ARCH__ >= 900
    cudaGridDependencySynchronize();
#endif
    int i = blockIdx.x * 256 + threadIdx.x;   // pair index, 50000 pairs
    if (i < N_NODES / 2) {
        float4 sd2 = ((const float4*)g_sd)[i];      // {ss0,deg0,ss1,deg1}
        float2 t2  = ((const float2*)g_t)[i];
        float di0 = rsqrtf(1.0f + sd2.y);
        float di1 = rsqrtf(1.0f + sd2.w);
        float z0 = di0 * (t2.x + sd2.x * di0) + g_c;
        float z1 = di1 * (t2.y + sd2.z * di1) + g_c;
        float2 o;
        o.x = 1.0f / (1.0f + expf(-z0));
        o.y = 1.0f / (1.0f + expf(-z1));
        ((float2*)out)[i] = o;
        sd2.y = 0.f; sd2.w = 0.f;                   // reset degrees, keep ss
        ((float4*)g_sd)[i] = sd2;
        ((float2*)g_t)[i] = make_float2(0.f, 0.f);
    }
}

static void launch_pdl(const void* fn, dim3 grid, dim3 block, void** args) {
    cudaLaunchConfig_t cfg = {};
    cfg.gridDim = grid;
    cfg.blockDim = block;
    cfg.dynamicSmemBytes = 0;
    cfg.stream = (cudaStream_t)0;
    cudaLaunchAttribute attr[1];
    attr[0].id = cudaLaunchAttributeProgrammaticStreamSerialization;
    attr[0].val.programmaticStreamSerializationAllowed = 1;
    cfg.attrs = attr;
    cfg.numAttrs = 1;
    cudaLaunchKernelExC(&cfg, fn, args);
}

extern "C" void kernel_launch(void* const* d_in, const int* in_sizes, int n_in,
                              void* d_out, int out_size) {
    const float* x   = (const float*)d_in[0];
    const int*   ei  = (const int*)d_in[1];   // [2, N_EDGES], materialized as int32
    const float* W   = (const float*)d_in[2];
    const float* b   = (const float*)d_in[3];
    const float* w2  = (const float*)d_in[4];
    const float* b2  = (const float*)d_in[5];
    float*       out = (float*)d_out;

    const int* src = ei;
    const int* dst = ei + N_EDGES;

    k_prep<<<1, 256>>>(W, b, w2, b2);

    {
        void* args[] = {(void*)&x, (void*)&dst};
        launch_pdl((const void*)k_dotdeg, dim3(DOT_BLOCKS), dim3(256), args);
    }
    {
        void* args[] = {(void*)&src, (void*)&dst};
        launch_pdl((const void*)k_scatter,
                   dim3((EDGE_PAIRS + 255) / 256), dim3(256), args);
    }
    {
        void* args[] = {(void*)&out};
        launch_pdl((const void*)k_out,
                   dim3((N_NODES / 2 + 255) / 256), dim3(256), args);
    }
}